// round 16
// baseline (speedup 1.0000x reference)
#include <cuda_runtime.h>
#include <cstdint>

#define NPTS   100000
#define PPROP  256
#define RFEAT  256
#define CO     21
#define NCHUNK 74
#define CHUNK  1352      // 74*1352 = 100048 >= 100000
#define CPAD   1536
#define NWORD  48        // mask words (44 used: 22 stages x 2)
#define SPTS   64        // points per stage (2 mask words)
#define NSTAGE 22        // 22*64 = 1408 >= 1352
#define PG     128       // proposals per block

// Scratch (__device__ globals: allocation-free rule)
__device__ uint32_t g_partial_bf[NCHUNK][PPROP][RFEAT / 2];   // 9.7 MB bf16x2
__device__ float    g_pcounts[NCHUNK][PPROP];
__device__ float    g_cls[PPROP * CO];
__device__ float    g_obj[PPROP * CO];

#define ADD_F32X2(out, a, b) \
    asm("add.rn.f32x2 %0, %1, %2;" : "=l"(out) : "l"(a), "l"(b))

// pack f32x2 (lo = even feat, hi = odd feat) -> bf16x2 (lo16 = even feat)
static __device__ __forceinline__ uint32_t pack_bf(unsigned long long p) {
    uint32_t lo, hi, r;
    asm("mov.b64 {%0, %1}, %2;" : "=r"(lo), "=r"(hi) : "l"(p));
    asm("cvt.rn.bf16x2.f32 %0, %1, %2;" : "=r"(r)
        : "f"(__uint_as_float(hi)), "f"(__uint_as_float(lo)));
    return r;
}

static __device__ __forceinline__ void mbar_init(uint32_t a, uint32_t c) {
    asm volatile("mbarrier.init.shared.b64 [%0], %1;" :: "r"(a), "r"(c) : "memory");
}
static __device__ __forceinline__ void mbar_expect_tx(uint32_t a, uint32_t bytes) {
    asm volatile("mbarrier.arrive.expect_tx.shared.b64 _, [%0], %1;"
                 :: "r"(a), "r"(bytes) : "memory");
}
static __device__ __forceinline__ void mbar_wait(uint32_t mbar, uint32_t parity) {
    uint32_t done;
    asm volatile("{\n\t.reg .pred p;\n\t"
                 "mbarrier.try_wait.parity.acquire.cta.shared::cta.b64 p, [%1], %2;\n\t"
                 "selp.b32 %0, 1, 0, p;\n\t}"
                 : "=r"(done) : "r"(mbar), "r"(parity) : "memory");
    if (!done) {
        asm volatile("{\n\t.reg .pred P1;\n\t"
                     "WL_%=:\n\t"
                     "mbarrier.try_wait.parity.acquire.cta.shared::cta.b64 P1, [%0], %1, 0x989680;\n\t"
                     "@P1 bra.uni WD_%=;\n\t"
                     "bra.uni WL_%=;\n\t"
                     "WD_%=:\n\t}" :: "r"(mbar), "r"(parity) : "memory");
    }
}
// One bulk DMA: contiguous GMEM -> SMEM, completion via mbarrier tx-bytes.
static __device__ __forceinline__ void bulk_copy(uint32_t dst_smem, const void* src,
                                                 uint32_t bytes, uint32_t mbar) {
    asm volatile("cp.async.bulk.shared::cluster.global.mbarrier::complete_tx::bytes "
                 "[%0], [%1], %2, [%3];"
                 :: "r"(dst_smem), "l"(src), "r"(bytes), "r"(mbar) : "memory");
}

struct PoolSmem {
    union {
        float4 sf[3][SPTS][64];   // 192 KB feature triple-buffer (f32)
        float4 sxyz4[CPAD];       // 24 KB padded xyz (phase A only)
    } u;
    unsigned smaskT[NWORD][PG];   // 24 KB bitmaps, word-major
    int      sgrp[PG];
    float    scnt[8][PG];
    float    scntTot[PG];
    unsigned long long mbar[3];
};
#define POOL_SMEM_BYTES ((int)sizeof(PoolSmem))

// ---------------------------------------------------------------------------
// Kernel 1: sparse ROI pooling, bulk-DMA triple-buffered + load-balanced.
// grid = (74 chunks, 2 groups of 128 props), block = 1024, 1 CTA/SM.
// Phase A: xyz -> bitmaps; exact counts -> rank-sort -> serpentine warp
//          assignment (4 props/warp) -> repack bitmaps warp-grouped.
// Phase B: 22 stages of 64 pts x 1KB features, one cp.async.bulk per stage,
//          PREFETCH DISTANCE 2 (DMA for st+2 issued at top of stage st into
//          the buffer freed by stage st-1's barrier; transfer fully hidden
//          behind 2 stages of scan). ONE __syncthreads per stage.
// Output: partial sums packed bf16x2.
// ---------------------------------------------------------------------------
__global__ __launch_bounds__(1024, 1)
void pool_kernel(const float* __restrict__ proposals,
                 const float* __restrict__ xyz,
                 const float* __restrict__ feats)
{
    extern __shared__ char smem_raw[];
    PoolSmem* s = reinterpret_cast<PoolSmem*>(smem_raw);

    const int chunk = blockIdx.x;
    const int pbase = blockIdx.y * PG;
    const int tid   = threadIdx.x;
    const int w     = tid >> 5;
    const int l     = tid & 31;
    const int pm    = tid & 127;  // proposal this thread masks
    const int q     = tid >> 7;   // point range [192q, 192q+192)

    const int base = chunk * CHUNK;
    const int nPts = (NPTS - base < CHUNK) ? (NPTS - base) : CHUNK;

    uint32_t mb[3];
#pragma unroll
    for (int i = 0; i < 3; i++)
        mb[i] = (uint32_t)__cvta_generic_to_shared(&s->mbar[i]);
    if (tid == 0) { mbar_init(mb[0], 1); mbar_init(mb[1], 1); mbar_init(mb[2], 1); }

    // ---- Phase A: stage xyz as padded float4 (pad 2.0 -> outside all boxes)
    {
        const float* gx = xyz + (size_t)base * 3;
#pragma unroll
        for (int k = 0; k < 2; k++) {
            const int j = tid + k * 1024;
            if (j < CPAD) {
                float x = 2.f, y = 2.f, z = 2.f;
                if (j < nPts) { x = gx[3*j]; y = gx[3*j+1]; z = gx[3*j+2]; }
                s->u.sxyz4[j] = make_float4(x, y, z, 0.f);
            }
        }
    }

    // Box bounds, bit-exact vs reference (no FMA contraction).
    float alox, ahix, aloy, ahiy, aloz, ahiz;
    {
        const float* pr = proposals + (size_t)(pbase + pm) * 6;
        const float cx = pr[0], cy = pr[1], cz = pr[2];
        const float hx = __fmul_rn(pr[3], 0.5f);
        const float hy = __fmul_rn(pr[4], 0.5f);
        const float hz = __fmul_rn(pr[5], 0.5f);
        alox = __fsub_rn(cx, hx);  ahix = __fadd_rn(cx, hx);
        aloy = __fsub_rn(cy, hy);  ahiy = __fadd_rn(cy, hy);
        aloz = __fsub_rn(cz, hz);  ahiz = __fadd_rn(cz, hz);
    }
    __syncthreads();   // xyz + mbar init visible

    // ---- Build masks: 6 words of 32 tests each (1 broadcast LDS.128/test)
    {
        float cnt = 0.f;
#pragma unroll
        for (int wd = 0; wd < 6; wd++) {
            unsigned bits = 0;
#pragma unroll
            for (int k = 0; k < 32; k++) {
                const float4 v = s->u.sxyz4[q * 192 + wd * 32 + k];
                const bool in = (v.x >= alox) & (v.x <= ahix) &
                                (v.y >= aloy) & (v.y <= ahiy) &
                                (v.z >= aloz) & (v.z <= ahiz);
                bits |= ((unsigned)in) << k;
            }
            s->smaskT[q * 6 + wd][pm] = bits;
            cnt += (float)__popc(bits);
        }
        s->scnt[q][pm] = cnt;
    }
    __syncthreads();

    // ---- Counts + balanced assignment ----
    if (tid < PG) {
        float c = 0.f;
#pragma unroll
        for (int k = 0; k < 8; k++) c += s->scnt[k][tid];
        s->scntTot[tid] = c;
        g_pcounts[chunk][pbase + tid] = c;
    }
    __syncthreads();
    if (tid < PG) {
        const float mine = s->scntTot[tid];
        int rank = 0;
        for (int p = 0; p < PG; p++) {
            const float v = s->scntTot[p];
            rank += (v > mine) || ((v == mine) && (p < tid));
        }
        const int round = rank >> 5;
        const int pos   = rank & 31;
        const int wdst  = (round & 1) ? (31 - pos) : pos;
        s->sgrp[wdst * 4 + round] = tid;
    }
    __syncthreads();
    // ---- Repack bitmaps into slot order ----
    {
        const int c  = tid & 127;
        const int qq = tid >> 7;
        const int src = s->sgrp[c];
        unsigned regs[6];
#pragma unroll
        for (int wd = 0; wd < 6; wd++) regs[wd] = s->smaskT[qq * 6 + wd][src];
        __syncthreads();
#pragma unroll
        for (int wd = 0; wd < 6; wd++) s->smaskT[qq * 6 + wd][c] = regs[wd];
    }
    __syncthreads();   // masks repacked; xyz area now reusable for features

    // ---- Phase B: triple-buffered bulk-DMA accumulation ----
    ulonglong2 accA[4], accB[4];
#pragma unroll
    for (int j = 0; j < 4; j++) {
        accA[j].x = 0ull; accA[j].y = 0ull;
        accB[j].x = 0ull; accB[j].y = 0ull;
    }

    uint32_t sfb[3];
#pragma unroll
    for (int i = 0; i < 3; i++)
        sfb[i] = (uint32_t)__cvta_generic_to_shared(&s->u.sf[i][0][0]);

    auto issue = [&](int st) {
        const int b = st % 3;
        const int t0 = st * SPTS;
        int rows = nPts - t0;
        if (rows > SPTS) rows = SPTS;
        const uint32_t bytes = (rows > 0) ? (uint32_t)rows * 1024u : 0u;
        mbar_expect_tx(mb[b], bytes);
        if (bytes)
            bulk_copy(sfb[b], feats + (size_t)(base + t0) * RFEAT, bytes, mb[b]);
    };

    if (tid == 0) { issue(0); issue(1); }

    int ph[3] = {0, 0, 0};
    for (int st = 0; st < NSTAGE; st++) {
        const int b = st % 3;
        mbar_wait(mb[b], ph[b]);
        ph[b] ^= 1;

        // prefetch distance 2: buffer (st+2)%3 was freed by stage st-1's
        // barrier (all warps past it), so tid 0 may refill immediately.
        if (tid == 0 && st + 2 < NSTAGE) issue(st + 2);

#pragma unroll
        for (int wd2 = 0; wd2 < 2; wd2++) {
            const int word = 2 * st + wd2;
            const uint4 mw =
                *reinterpret_cast<const uint4*>(&s->smaskT[word][w << 2]);
            const int ibase = wd2 << 5;

#define SCAN_ONE(MWORD, J)                                                    \
            {                                                                 \
                unsigned m = (MWORD);                                         \
                while (m) {                                                   \
                    const int i = ibase + __ffs(m) - 1;                       \
                    m &= m - 1;                                               \
                    const ulonglong2 va =                                     \
                        *reinterpret_cast<const ulonglong2*>(&s->u.sf[b][i][l]);      \
                    const ulonglong2 vb =                                     \
                        *reinterpret_cast<const ulonglong2*>(&s->u.sf[b][i][l + 32]); \
                    ADD_F32X2(accA[J].x, accA[J].x, va.x);                    \
                    ADD_F32X2(accA[J].y, accA[J].y, va.y);                    \
                    ADD_F32X2(accB[J].x, accB[J].x, vb.x);                    \
                    ADD_F32X2(accB[J].y, accB[J].y, vb.y);                    \
                }                                                             \
            }
            SCAN_ONE(mw.x, 0)
            SCAN_ONE(mw.y, 1)
            SCAN_ONE(mw.z, 2)
            SCAN_ONE(mw.w, 3)
#undef SCAN_ONE
        }
        __syncthreads();   // stage st consumed by ALL warps (frees buffer b)
    }

    // Write partial sums as bf16x2 (prop index via balanced assignment)
#pragma unroll
    for (int j = 0; j < 4; j++) {
        const int prop = s->sgrp[(w << 2) + j];
        uint32_t* row = &g_partial_bf[chunk][pbase + prop][0];
        reinterpret_cast<uint2*>(row)[l] =
            make_uint2(pack_bf(accA[j].x), pack_bf(accA[j].y));
        reinterpret_cast<uint2*>(row + 64)[l] =
            make_uint2(pack_bf(accB[j].x), pack_bf(accB[j].y));
    }
}

// ---------------------------------------------------------------------------
// Kernel 2: reduce bf16 partials -> roi -> logits (warp-parallel dots).
// grid = 256 (block per proposal), block = 256.
// ---------------------------------------------------------------------------
__global__ __launch_bounds__(256)
void reduce_kernel(const float* __restrict__ W_cls, const float* __restrict__ b_cls,
                   const float* __restrict__ W_obj, const float* __restrict__ b_obj)
{
    const int p   = blockIdx.x;
    const int tid = threadIdx.x;
    const int w   = tid >> 5;
    const int l   = tid & 31;

    __shared__ float roi[RFEAT];
    __shared__ float sc[8];

    float e0 = 0.f, o0 = 0.f, e1 = 0.f, o1 = 0.f;
    if (tid < 128) {
        const uint32_t* colp = &g_partial_bf[0][p][tid];
        const size_t stride = (size_t)PPROP * (RFEAT / 2);
#pragma unroll
        for (int c = 0; c < NCHUNK; c += 2) {
            const uint32_t ua = colp[(size_t)c * stride];
            const uint32_t ub = colp[(size_t)(c + 1) * stride];
            e0 += __uint_as_float(ua << 16);
            o0 += __uint_as_float(ua & 0xFFFF0000u);
            e1 += __uint_as_float(ub << 16);
            o1 += __uint_as_float(ub & 0xFFFF0000u);
        }
    }

    float cv = (tid < NCHUNK) ? g_pcounts[tid][p] : 0.f;
#pragma unroll
    for (int o = 16; o > 0; o >>= 1) cv += __shfl_down_sync(0xffffffffu, cv, o);
    if (l == 0) sc[w] = cv;
    __syncthreads();
    if (tid == 0) {
        float t = 0.f;
#pragma unroll
        for (int i = 0; i < 8; i++) t += sc[i];
        sc[0] = 1.0f / fmaxf(t, 1.0f);
    }
    __syncthreads();
    if (tid < 128) {
        roi[2 * tid]     = (e0 + e1) * sc[0];
        roi[2 * tid + 1] = (o0 + o1) * sc[0];
    }
    __syncthreads();

    for (int o = w; o < 2 * CO; o += 8) {
        const bool isobj = o >= CO;
        const int  j     = isobj ? o - CO : o;
        const float* Wm  = isobj ? W_obj : W_cls;
        float a = 0.f;
#pragma unroll
        for (int f = l; f < RFEAT; f += 32) a += roi[f] * Wm[f * CO + j];
#pragma unroll
        for (int off = 16; off > 0; off >>= 1)
            a += __shfl_xor_sync(0xffffffffu, a, off);
        if (l == 0)
            (isobj ? g_obj : g_cls)[p * CO + j] = a + (isobj ? b_obj[j] : b_cls[j]);
    }
}

// ---------------------------------------------------------------------------
// Kernel 3: softmaxes + product. 1 block, 1024 threads.
// ---------------------------------------------------------------------------
__global__ __launch_bounds__(1024)
void softmax_kernel(float* __restrict__ out)
{
    const int tid = threadIdx.x;
    __shared__ float sobj[PPROP * CO];
    __shared__ float red[CO][48];
    __shared__ float cmax[CO], cinv[CO];

    for (int e = tid; e < PPROP * CO; e += 1024) sobj[e] = g_obj[e];
    __syncthreads();

    const int c = tid / 48;
    const int r = tid % 48;

    if (tid < 1008) {
        float m = -3.4e38f;
        for (int p = r; p < PPROP; p += 48) m = fmaxf(m, sobj[p * CO + c]);
        red[c][r] = m;
    }
    __syncthreads();
    if (tid < CO) {
        float m = red[tid][0];
#pragma unroll
        for (int k = 1; k < 48; k++) m = fmaxf(m, red[tid][k]);
        cmax[tid] = m;
    }
    __syncthreads();
    if (tid < 1008) {
        const float m = cmax[c];
        float sm = 0.f;
        for (int p = r; p < PPROP; p += 48) {
            const float e = expf(sobj[p * CO + c] - m);
            sobj[p * CO + c] = e;
            sm += e;
        }
        red[c][r] = sm;
    }
    __syncthreads();
    if (tid < CO) {
        float sm = 0.f;
#pragma unroll
        for (int k = 0; k < 48; k++) sm += red[tid][k];
        cinv[tid] = 1.0f / sm;
    }
    __syncthreads();

    if (tid < 512) {
        const int row  = tid >> 1;
        const int half = tid & 1;
        float lg[CO];
        float m = -3.4e38f;
#pragma unroll
        for (int j = 0; j < CO; j++) { lg[j] = g_cls[row * CO + j]; m = fmaxf(m, lg[j]); }
        float sm = 0.f;
#pragma unroll
        for (int j = 0; j < CO; j++) { lg[j] = expf(lg[j] - m); sm += lg[j]; }
        const float invs = 1.0f / sm;
        if (half == 0) {
#pragma unroll
            for (int j = 0; j < 11; j++)
                out[row * CO + j] = lg[j] * invs * sobj[row * CO + j] * cinv[j];
        } else {
#pragma unroll
            for (int j = 11; j < CO; j++)
                out[row * CO + j] = lg[j] * invs * sobj[row * CO + j] * cinv[j];
        }
    }
}

// ---------------------------------------------------------------------------
extern "C" void kernel_launch(void* const* d_in, const int* in_sizes, int n_in,
                              void* d_out, int out_size)
{
    const float* proposals = (const float*)d_in[0];
    const float* input_xyz = (const float*)d_in[1];
    const float* seg_feats = (const float*)d_in[2];
    const float* W_cls     = (const float*)d_in[3];
    const float* b_cls     = (const float*)d_in[4];
    const float* W_obj     = (const float*)d_in[5];
    const float* b_obj     = (const float*)d_in[6];
    float* out = (float*)d_out;

    (void)in_sizes; (void)n_in; (void)out_size;

    cudaFuncSetAttribute(pool_kernel,
                         cudaFuncAttributeMaxDynamicSharedMemorySize,
                         POOL_SMEM_BYTES);
    pool_kernel<<<dim3(NCHUNK, 2), 1024, POOL_SMEM_BYTES>>>(proposals, input_xyz, seg_feats);
    reduce_kernel<<<PPROP, 256>>>(W_cls, b_cls, W_obj, b_obj);
    softmax_kernel<<<1, 1024>>>(out);
}